// round 9
// baseline (speedup 1.0000x reference)
#include <cuda_runtime.h>
#include <cuda_bf16.h>
#include <cstdint>

#define D_MODEL  1024
#define N_HEADS  16
#define HEAD_DIM 64
#define BATCH    2
#define SEQ      2048
#define M_TOT    (BATCH * SEQ)   // 4096
#define WSZ      (D_MODEL * D_MODEL)

// ---------------- scratch ----------------
__device__ __align__(1024) __nv_bfloat16 g_qhi[M_TOT * D_MODEL];
__device__ __align__(1024) __nv_bfloat16 g_qlo[M_TOT * D_MODEL];
__device__ __align__(1024) __nv_bfloat16 g_khi[M_TOT * D_MODEL];
__device__ __align__(1024) __nv_bfloat16 g_klo[M_TOT * D_MODEL];
__device__ __align__(1024) __nv_bfloat16 g_vhi[M_TOT * D_MODEL];
__device__ __align__(1024) __nv_bfloat16 g_vlo[M_TOT * D_MODEL];
__device__ __align__(1024) __nv_bfloat16 g_yhi[M_TOT * D_MODEL];
__device__ __align__(1024) __nv_bfloat16 g_ylo[M_TOT * D_MODEL];
__device__ __align__(1024) __nv_bfloat16 g_xhi[M_TOT * D_MODEL];
__device__ __align__(1024) __nv_bfloat16 g_xlo[M_TOT * D_MODEL];
__device__ __align__(1024) __nv_bfloat16 g_whi[4u * WSZ];
__device__ __align__(1024) __nv_bfloat16 g_wlo[4u * WSZ];

// ---------------- helpers ----------------
__device__ __forceinline__ uint32_t smem_u32(const void* p) {
    uint32_t a;
    asm("{ .reg .u64 t; cvta.to.shared.u64 t, %1; cvt.u32.u64 %0, t; }" : "=r"(a) : "l"(p));
    return a;
}
__device__ __forceinline__ uint32_t swz128(uint32_t off) { return off ^ ((off >> 3) & 0x70); }
__device__ __forceinline__ uint32_t swz64(uint32_t off)  { return off ^ ((off >> 3) & 0x30); }
__device__ __forceinline__ void cp16(uint32_t s, const void* g) {
    asm volatile("cp.async.cg.shared.global [%0], [%1], 16;" :: "r"(s), "l"(g));
}
#define CP_COMMIT() asm volatile("cp.async.commit_group;" ::: "memory")
#define CP_WAIT(n)  asm volatile("cp.async.wait_group %0;" :: "n"(n) : "memory")

__device__ __forceinline__ void ldsm4(uint32_t r[4], uint32_t addr) {
    asm volatile("ldmatrix.sync.aligned.m8n8.x4.shared.b16 {%0,%1,%2,%3}, [%4];"
                 : "=r"(r[0]), "=r"(r[1]), "=r"(r[2]), "=r"(r[3]) : "r"(addr));
}
__device__ __forceinline__ void ldsm4t(uint32_t r[4], uint32_t addr) {
    asm volatile("ldmatrix.sync.aligned.m8n8.x4.trans.shared.b16 {%0,%1,%2,%3}, [%4];"
                 : "=r"(r[0]), "=r"(r[1]), "=r"(r[2]), "=r"(r[3]) : "r"(addr));
}
__device__ __forceinline__ void mma_bf16(float d[4], const uint32_t a[4],
                                         uint32_t b0, uint32_t b1) {
    asm volatile(
        "mma.sync.aligned.m16n8k16.row.col.f32.bf16.bf16.f32 "
        "{%0,%1,%2,%3}, {%4,%5,%6,%7}, {%8,%9}, {%0,%1,%2,%3};"
        : "+f"(d[0]), "+f"(d[1]), "+f"(d[2]), "+f"(d[3])
        : "r"(a[0]), "r"(a[1]), "r"(a[2]), "r"(a[3]), "r"(b0), "r"(b1));
}
__device__ __forceinline__ uint32_t pack_bf16x2(float lo, float hi) {
    uint32_t r;
    asm("cvt.rn.bf16x2.f32 %0, %1, %2;" : "=r"(r) : "f"(hi), "f"(lo));
    return r;
}
__device__ __forceinline__ void split2(float v0, float v1, uint32_t& ph, uint32_t& pl) {
    ph = pack_bf16x2(v0, v1);
    float r0 = __uint_as_float(ph << 16);
    float r1 = __uint_as_float(ph & 0xffff0000u);
    pl = pack_bf16x2(v0 - r0, v1 - r1);
}

// ---------------- fused split: x + 4 weights in one launch ----------------
#define XN4 (M_TOT * D_MODEL / 4)
#define WN4 (WSZ / 4)

__global__ __launch_bounds__(256) void split_all(
    const float4* __restrict__ x,
    const float4* __restrict__ wq, const float4* __restrict__ wk,
    const float4* __restrict__ wv, const float4* __restrict__ wp,
    __nv_bfloat162* __restrict__ xhi, __nv_bfloat162* __restrict__ xlo,
    __nv_bfloat162* __restrict__ whi, __nv_bfloat162* __restrict__ wlo)
{
    int i = blockIdx.x * 256 + threadIdx.x;
    const float4* src;
    __nv_bfloat162 *hi, *lo;
    int off;
    if (i < XN4) {
        src = x; off = i; hi = xhi; lo = xlo;
    } else {
        int j = i - XN4;
        int w = j >> 18;
        off = j & (WN4 - 1);
        src = (w == 0) ? wq : (w == 1) ? wk : (w == 2) ? wv : wp;
        hi = whi + (size_t)w * (WSZ / 2);
        lo = wlo + (size_t)w * (WSZ / 2);
    }
    float4 v = src[off];
    uint32_t h0, l0, h1, l1;
    split2(v.x, v.y, h0, l0);
    split2(v.z, v.w, h1, l1);
    *(uint32_t*)&hi[2 * off + 0] = h0;
    *(uint32_t*)&hi[2 * off + 1] = h1;
    *(uint32_t*)&lo[2 * off + 0] = l0;
    *(uint32_t*)&lo[2 * off + 1] = l1;
}

// ---------------- HMMA split-bf16 GEMM (BK=32, SW64, 3-stage, 1 sync/chunk) ----------------
#define T_B    8192                   // 128 rows x 32 bf16 (64B), SW64
#define STG_B  (4 * T_B)              // 32768
#define NSTG   3
#define GEMM_SMEM (NSTG * STG_B)      // 98304 -> 2 CTAs/SM (192KB <= 228KB)
#define KCHUNKS (D_MODEL / 32)        // 32

__device__ __forceinline__ void load_stage(
    uint32_t sbase, const __nv_bfloat16* a0, const __nv_bfloat16* a1,
    const __nv_bfloat16* b0, const __nv_bfloat16* b1, int kc, int tid)
{
    const __nv_bfloat16* gs[4] = {a0, a1, b0, b1};
    #pragma unroll
    for (int t = 0; t < 4; t++) {
        uint32_t tb = sbase + t * T_B;
        const __nv_bfloat16* g = gs[t] + kc * 32;
        #pragma unroll
        for (int i = 0; i < 2; i++) {
            int u = i * 256 + tid;            // 0..511 16B-chunks
            int r = u >> 2, c4 = u & 3;
            cp16(tb + swz64(r * 64 + c4 * 16), g + (size_t)r * D_MODEL + c4 * 8);
        }
    }
}

template <bool SPLIT>
__global__ __launch_bounds__(256, 2) void gemm_hmma(
    const __nv_bfloat16* __restrict__ Ahi, const __nv_bfloat16* __restrict__ Alo,
    const __nv_bfloat16* __restrict__ Whi, const __nv_bfloat16* __restrict__ Wlo,
    const float* __restrict__ biasQ, const float* __restrict__ biasK,
    const float* __restrict__ biasV,
    float* __restrict__ C,
    __nv_bfloat16* __restrict__ QH, __nv_bfloat16* __restrict__ QL,
    __nv_bfloat16* __restrict__ KH, __nv_bfloat16* __restrict__ KL,
    __nv_bfloat16* __restrict__ VH, __nv_bfloat16* __restrict__ VL)
{
    extern __shared__ __align__(1024) char smem[];
    const uint32_t sb = smem_u32(smem);
    const int tid = threadIdx.x;
    const int wid = tid >> 5, lane = tid & 31;
    const int which = blockIdx.x >> 3;
    const int n0 = (blockIdx.x & 7) * 128;
    const int m0 = blockIdx.y * 128;
    const int wm = (wid >> 1) * 32;
    const int wn = (wid & 1) * 64;
    const int gid = lane >> 2, tig = lane & 3;

    const float* bias = (which == 0) ? biasQ : (which == 1) ? biasK : biasV;
    __nv_bfloat16* Chi = (which == 0) ? QH : (which == 1) ? KH : VH;
    __nv_bfloat16* Clo = (which == 0) ? QL : (which == 1) ? KL : VL;

    const __nv_bfloat16* a0 = Ahi + (size_t)m0 * D_MODEL;
    const __nv_bfloat16* a1 = Alo + (size_t)m0 * D_MODEL;
    const __nv_bfloat16* b0 = Whi + (size_t)which * WSZ + (size_t)n0 * D_MODEL;
    const __nv_bfloat16* b1 = Wlo + (size_t)which * WSZ + (size_t)n0 * D_MODEL;

    const int a_row  = wm + (lane & 15);
    const int a_byte = ((lane >> 4) & 1) * 16;
    const int b_row  = wn + ((lane >> 4) & 1) * 8 + (lane & 7);
    const int b_byte = ((lane >> 3) & 1) * 16;

    float d[2][8][4];
    #pragma unroll
    for (int i = 0; i < 2; i++)
        #pragma unroll
        for (int j = 0; j < 8; j++)
            #pragma unroll
            for (int c = 0; c < 4; c++) d[i][j][c] = 0.0f;

    // prologue: stages 0,1
    load_stage(sb + 0 * STG_B, a0, a1, b0, b1, 0, tid);
    CP_COMMIT();
    load_stage(sb + 1 * STG_B, a0, a1, b0, b1, 1, tid);
    CP_COMMIT();

    for (int kc = 0; kc < KCHUNKS; kc++) {
        if (kc + 1 < KCHUNKS) { CP_WAIT(1); } else { CP_WAIT(0); }   // stage kc ready
        __syncthreads();                   // all warps done with stage kc-1 compute
        if (kc + 2 < KCHUNKS) {            // prefetch 2 ahead into buffer (kc-1)%3
            load_stage(sb + ((kc + 2) % NSTG) * STG_B, a0, a1, b0, b1, kc + 2, tid);
            CP_COMMIT();
        }
        const uint32_t st = sb + (kc % NSTG) * STG_B;

        #pragma unroll
        for (int ks = 0; ks < 2; ks++) {
            uint32_t ah[2][4], al[2][4];
            #pragma unroll
            for (int am = 0; am < 2; am++) {
                uint32_t off = swz64((uint32_t)(a_row + am * 16) * 64 + a_byte + ks * 32);
                ldsm4(ah[am], st + off);
                ldsm4(al[am], st + T_B + off);
            }
            uint32_t bh[8][2], bl[8][2];
            #pragma unroll
            for (int pr = 0; pr < 4; pr++) {
                uint32_t off = swz64((uint32_t)(b_row + pr * 16) * 64 + b_byte + ks * 32);
                uint32_t r[4];
                ldsm4(r, st + 2 * T_B + off);
                bh[2 * pr][0] = r[0]; bh[2 * pr][1] = r[1];
                bh[2 * pr + 1][0] = r[2]; bh[2 * pr + 1][1] = r[3];
                ldsm4(r, st + 3 * T_B + off);
                bl[2 * pr][0] = r[0]; bl[2 * pr][1] = r[1];
                bl[2 * pr + 1][0] = r[2]; bl[2 * pr + 1][1] = r[3];
            }
            #pragma unroll
            for (int am = 0; am < 2; am++)
                #pragma unroll
                for (int bn = 0; bn < 8; bn++) {
                    mma_bf16(d[am][bn], ah[am], bh[bn][0], bh[bn][1]);
                    mma_bf16(d[am][bn], ah[am], bl[bn][0], bl[bn][1]);
                    mma_bf16(d[am][bn], al[am], bh[bn][0], bh[bn][1]);
                }
        }
    }

    #pragma unroll
    for (int am = 0; am < 2; am++) {
        const int row = m0 + wm + am * 16 + gid;
        #pragma unroll
        for (int bn = 0; bn < 8; bn++) {
            const int col = n0 + wn + bn * 8 + tig * 2;
            const float bv0 = __ldg(&bias[col]);
            const float bv1 = __ldg(&bias[col + 1]);
            float v0 = d[am][bn][0] + bv0, v1 = d[am][bn][1] + bv1;
            float v2 = d[am][bn][2] + bv0, v3 = d[am][bn][3] + bv1;
            if (SPLIT) {
                uint32_t h, l;
                split2(v0, v1, h, l);
                *(uint32_t*)&Chi[(size_t)row * D_MODEL + col] = h;
                *(uint32_t*)&Clo[(size_t)row * D_MODEL + col] = l;
                split2(v2, v3, h, l);
                *(uint32_t*)&Chi[(size_t)(row + 8) * D_MODEL + col] = h;
                *(uint32_t*)&Clo[(size_t)(row + 8) * D_MODEL + col] = l;
            } else {
                *(float2*)&C[(size_t)row * D_MODEL + col] = make_float2(v0, v1);
                *(float2*)&C[(size_t)(row + 8) * D_MODEL + col] = make_float2(v2, v3);
            }
        }
    }
}

// ---------------- HMMA flash attention (split-bf16, LPT, 3-stage, 1 sync/tile) ----------------
#define AQ 128
#define KV_STG 32768
#define KV_NSTG 3
#define ATT_SMEM (2 * AQ * 128 + KV_NSTG * KV_STG)   // 131072

__device__ __forceinline__ void attn_load_kv(
    uint32_t dst, const __nv_bfloat16* kh, const __nv_bfloat16* kl,
    const __nv_bfloat16* vh, const __nv_bfloat16* vl, int tid)
{
    const __nv_bfloat16* srcs[4] = {kh, kl, vh, vl};
    #pragma unroll
    for (int t = 0; t < 4; t++)
        #pragma unroll
        for (int i = 0; i < 2; i++) {
            int u = i * 256 + tid;
            int r = u >> 3, c = u & 7;
            cp16(dst + t * 8192 + swz128(r * 128 + c * 16),
                 srcs[t] + (size_t)r * D_MODEL + c * 8);
        }
}

__global__ __launch_bounds__(256) void attn_hmma(
    const __nv_bfloat16* __restrict__ Qhi, const __nv_bfloat16* __restrict__ Qlo,
    const __nv_bfloat16* __restrict__ Khi, const __nv_bfloat16* __restrict__ Klo,
    const __nv_bfloat16* __restrict__ Vhi, const __nv_bfloat16* __restrict__ Vlo,
    __nv_bfloat16* __restrict__ Yhi, __nv_bfloat16* __restrict__ Ylo)
{
    extern __shared__ __align__(1024) char smA[];
    const uint32_t sb = smem_u32(smA);
    const int tid = threadIdx.x, wid = tid >> 5, lane = tid & 31;
    const int gid = lane >> 2, tig = lane & 3;
    const int qblk = gridDim.y - 1 - blockIdx.y;   // LPT
    const int bh = blockIdx.x;
    const int b = bh >> 4, h = bh & 15;
    const size_t base = ((size_t)b * SEQ) * D_MODEL + (size_t)h * HEAD_DIM;

    const uint32_t sQh = sb;
    const uint32_t sQl = sb + AQ * 128;
    const uint32_t sKV = sb + 2 * AQ * 128;
    const int nkt = 2 * qblk + 2;

    // group A: Q hi/lo
    {
        const __nv_bfloat16* q0 = Qhi + base + (size_t)qblk * AQ * D_MODEL;
        const __nv_bfloat16* q1 = Qlo + base + (size_t)qblk * AQ * D_MODEL;
        #pragma unroll
        for (int i = 0; i < 4; i++) {
            int u = i * 256 + tid;
            int r = u >> 3, c = u & 7;
            cp16(sQh + swz128(r * 128 + c * 16), q0 + (size_t)r * D_MODEL + c * 8);
            cp16(sQl + swz128(r * 128 + c * 16), q1 + (size_t)r * D_MODEL + c * 8);
        }
    }
    CP_COMMIT();
    // groups B,C: KV tiles 0,1 (nkt >= 2 always)
    attn_load_kv(sKV + 0 * KV_STG, Khi + base, Klo + base, Vhi + base, Vlo + base, tid);
    CP_COMMIT();
    {
        const size_t k1 = base + (size_t)64 * D_MODEL;
        attn_load_kv(sKV + 1 * KV_STG, Khi + k1, Klo + k1, Vhi + k1, Vlo + k1, tid);
    }
    CP_COMMIT();

    CP_WAIT(2);            // Q ready
    __syncthreads();

    uint32_t qh[4][4], ql[4][4];
    {
        const int ar = wid * 16 + (lane & 15);
        const int ab = ((lane >> 4) & 1) * 16;
        #pragma unroll
        for (int ks = 0; ks < 4; ks++) {
            ldsm4(qh[ks], sQh + swz128((uint32_t)ar * 128 + ab + ks * 32));
            ldsm4(ql[ks], sQl + swz128((uint32_t)ar * 128 + ab + ks * 32));
        }
    }

    float o[8][4];
    #pragma unroll
    for (int nt = 0; nt < 8; nt++)
        #pragma unroll
        for (int j = 0; j < 4; j++) o[nt][j] = 0.0f;
    float m0 = -1e30f, m1 = -1e30f, l0 = 0.0f, l1 = 0.0f;

    const int qr0 = qblk * AQ + wid * 16 + gid;
    const int row_min = qblk * AQ + wid * 16;
    const int row_max = row_min + 15;

    const int sbr = ((lane >> 4) & 1) * 8 + (lane & 7);
    const int sbb = ((lane >> 3) & 1) * 16;
    const int vrr = lane & 15;
    const int vbb = ((lane >> 4) & 1) * 16;

    const float SC = 0.125f * 1.44269504f;

    for (int kt = 0; kt < nkt; kt++) {
        if (kt + 1 < nkt) { CP_WAIT(1); } else { CP_WAIT(0); }   // KV tile kt ready
        __syncthreads();                // all warps done with stage kt-1
        if (kt + 2 < nkt) {             // prefetch 2 ahead into stage (kt-1)%3
            const size_t koff = base + (size_t)(kt + 2) * 64 * D_MODEL;
            attn_load_kv(sKV + (uint32_t)((kt + 2) % KV_NSTG) * KV_STG,
                         Khi + koff, Klo + koff, Vhi + koff, Vlo + koff, tid);
            CP_COMMIT();
        }
        const uint32_t st = sKV + (uint32_t)(kt % KV_NSTG) * KV_STG;

        if (kt * 64 > row_max) continue;

        float s[8][4];
        #pragma unroll
        for (int nt = 0; nt < 8; nt++)
            #pragma unroll
            for (int j = 0; j < 4; j++) s[nt][j] = 0.0f;

        #pragma unroll
        for (int ks = 0; ks < 4; ks++) {
            #pragma unroll
            for (int np = 0; np < 4; np++) {
                uint32_t off = swz128((uint32_t)(np * 16 + sbr) * 128 + sbb + ks * 32);
                uint32_t rh[4], rl[4];
                ldsm4(rh, st + off);
                ldsm4(rl, st + 8192 + off);
                mma_bf16(s[2 * np],     qh[ks], rh[0], rh[1]);
                mma_bf16(s[2 * np],     qh[ks], rl[0], rl[1]);
                mma_bf16(s[2 * np],     ql[ks], rh[0], rh[1]);
                mma_bf16(s[2 * np + 1], qh[ks], rh[2], rh[3]);
                mma_bf16(s[2 * np + 1], qh[ks], rl[2], rl[3]);
                mma_bf16(s[2 * np + 1], ql[ks], rh[2], rh[3]);
            }
        }

        const bool need_mask = (kt * 64 + 63 > row_min);
        #pragma unroll
        for (int nt = 0; nt < 8; nt++) {
            #pragma unroll
            for (int j = 0; j < 4; j++) s[nt][j] *= SC;
            if (need_mask) {
                const int kc = kt * 64 + nt * 8 + 2 * tig;
                if (kc     > qr0)     s[nt][0] = -1e30f;
                if (kc + 1 > qr0)     s[nt][1] = -1e30f;
                if (kc     > qr0 + 8) s[nt][2] = -1e30f;
                if (kc + 1 > qr0 + 8) s[nt][3] = -1e30f;
            }
        }

        float mx0 = -1e30f, mx1 = -1e30f;
        #pragma unroll
        for (int nt = 0; nt < 8; nt++) {
            mx0 = fmaxf(mx0, fmaxf(s[nt][0], s[nt][1]));
            mx1 = fmaxf(mx1, fmaxf(s[nt][2], s[nt][3]));
        }
        mx0 = fmaxf(mx0, __shfl_xor_sync(0xffffffffu, mx0, 1));
        mx0 = fmaxf(mx0, __shfl_xor_sync(0xffffffffu, mx0, 2));
        mx1 = fmaxf(mx1, __shfl_xor_sync(0xffffffffu, mx1, 1));
        mx1 = fmaxf(mx1, __shfl_xor_sync(0xffffffffu, mx1, 2));
        const float nm0 = fmaxf(m0, mx0), nm1 = fmaxf(m1, mx1);
        const float c0 = exp2f(m0 - nm0), c1 = exp2f(m1 - nm1);
        m0 = nm0; m1 = nm1;

        uint32_t pAh[8], pBh[8], pAl[8], pBl[8];
        float la0 = 0.0f, la1 = 0.0f;
        #pragma unroll
        for (int nt = 0; nt < 8; nt++) {
            float p0 = exp2f(s[nt][0] - m0), p1 = exp2f(s[nt][1] - m0);
            float p2 = exp2f(s[nt][2] - m1), p3 = exp2f(s[nt][3] - m1);
            la0 += p0 + p1; la1 += p2 + p3;
            split2(p0, p1, pAh[nt], pAl[nt]);
            split2(p2, p3, pBh[nt], pBl[nt]);
        }
        la0 += __shfl_xor_sync(0xffffffffu, la0, 1);
        la0 += __shfl_xor_sync(0xffffffffu, la0, 2);
        la1 += __shfl_xor_sync(0xffffffffu, la1, 1);
        la1 += __shfl_xor_sync(0xffffffffu, la1, 2);
        l0 = l0 * c0 + la0;
        l1 = l1 * c1 + la1;
        #pragma unroll
        for (int nt = 0; nt < 8; nt++) {
            o[nt][0] *= c0; o[nt][1] *= c0;
            o[nt][2] *= c1; o[nt][3] *= c1;
        }

        #pragma unroll
        for (int kk = 0; kk < 4; kk++) {
            uint32_t aH[4] = {pAh[2 * kk], pBh[2 * kk], pAh[2 * kk + 1], pBh[2 * kk + 1]};
            uint32_t aL[4] = {pAl[2 * kk], pBl[2 * kk], pAl[2 * kk + 1], pBl[2 * kk + 1]};
            #pragma unroll
            for (int np = 0; np < 4; np++) {
                uint32_t off = swz128((uint32_t)(kk * 16 + vrr) * 128 + vbb + np * 32);
                uint32_t rh[4], rl[4];
                ldsm4t(rh, st + 16384 + off);
                ldsm4t(rl, st + 24576 + off);
                mma_bf16(o[2 * np],     aH, rh[0], rh[1]);
                mma_bf16(o[2 * np],     aH, rl[0], rl[1]);
                mma_bf16(o[2 * np],     aL, rh[0], rh[1]);
                mma_bf16(o[2 * np + 1], aH, rh[2], rh[3]);
                mma_bf16(o[2 * np + 1], aH, rl[2], rl[3]);
                mma_bf16(o[2 * np + 1], aL, rh[2], rh[3]);
            }
        }
    }

    const float i0 = 1.0f / l0, i1 = 1.0f / l1;
    const size_t r0a = base + (size_t)qr0 * D_MODEL;
    const size_t r1a = base + (size_t)(qr0 + 8) * D_MODEL;
    #pragma unroll
    for (int nt = 0; nt < 8; nt++) {
        const int col = nt * 8 + 2 * tig;
        uint32_t hjk, ljk;
        split2(o[nt][0] * i0, o[nt][1] * i0, hjk, ljk);
        *(uint32_t*)&Yhi[r0a + col] = hjk;
        *(uint32_t*)&Ylo[r0a + col] = ljk;
        split2(o[nt][2] * i1, o[nt][3] * i1, hjk, ljk);
        *(uint32_t*)&Yhi[r1a + col] = hjk;
        *(uint32_t*)&Ylo[r1a + col] = ljk;
    }
}

// ---------------- launch ----------------
extern "C" void kernel_launch(void* const* d_in, const int* in_sizes, int n_in,
                              void* d_out, int out_size)
{
    const float* x  = (const float*)d_in[0];
    const float* Wq = (const float*)d_in[1];
    const float* bq = (const float*)d_in[2];
    const float* Wk = (const float*)d_in[3];
    const float* bk = (const float*)d_in[4];
    const float* Wv = (const float*)d_in[5];
    const float* bv = (const float*)d_in[6];
    const float* Wp = (const float*)d_in[7];
    const float* bp = (const float*)d_in[8];
    float* out = (float*)d_out;

    __nv_bfloat16 *qhi, *qlo, *khi, *klo, *vhi, *vlo, *yhi, *ylo, *xhi, *xlo, *whi, *wlo;
    cudaGetSymbolAddress((void**)&qhi, g_qhi);
    cudaGetSymbolAddress((void**)&qlo, g_qlo);
    cudaGetSymbolAddress((void**)&khi, g_khi);
    cudaGetSymbolAddress((void**)&klo, g_klo);
    cudaGetSymbolAddress((void**)&vhi, g_vhi);
    cudaGetSymbolAddress((void**)&vlo, g_vlo);
    cudaGetSymbolAddress((void**)&yhi, g_yhi);
    cudaGetSymbolAddress((void**)&ylo, g_ylo);
    cudaGetSymbolAddress((void**)&xhi, g_xhi);
    cudaGetSymbolAddress((void**)&xlo, g_xlo);
    cudaGetSymbolAddress((void**)&whi, g_whi);
    cudaGetSymbolAddress((void**)&wlo, g_wlo);

    cudaFuncSetAttribute(gemm_hmma<true>,
                         cudaFuncAttributeMaxDynamicSharedMemorySize, GEMM_SMEM);
    cudaFuncSetAttribute(gemm_hmma<false>,
                         cudaFuncAttributeMaxDynamicSharedMemorySize, GEMM_SMEM);
    cudaFuncSetAttribute(attn_hmma,
                         cudaFuncAttributeMaxDynamicSharedMemorySize, ATT_SMEM);

    split_all<<<(XN4 + 4 * WN4) / 256, 256>>>(
        (const float4*)x, (const float4*)Wq, (const float4*)Wk,
        (const float4*)Wv, (const float4*)Wp,
        (__nv_bfloat162*)xhi, (__nv_bfloat162*)xlo,
        (__nv_bfloat162*)whi, (__nv_bfloat162*)wlo);

    gemm_hmma<true><<<dim3(24, 32), 256, GEMM_SMEM>>>(
        xhi, xlo, whi, wlo, bq, bk, bv,
        nullptr, qhi, qlo, khi, klo, vhi, vlo);

    attn_hmma<<<dim3(BATCH * N_HEADS, SEQ / AQ), 256, ATT_SMEM>>>(
        qhi, qlo, khi, klo, vhi, vlo, yhi, ylo);

    gemm_hmma<false><<<dim3(8, 32), 256, GEMM_SMEM>>>(
        yhi, ylo, whi + 3u * WSZ, wlo + 3u * WSZ, bp, nullptr, nullptr,
        out, nullptr, nullptr, nullptr, nullptr, nullptr, nullptr);
}

// round 10
// speedup vs baseline: 1.0458x; 1.0458x over previous
#include <cuda_runtime.h>
#include <cuda_bf16.h>
#include <cuda_fp16.h>
#include <cstdint>

#define D_MODEL  1024
#define N_HEADS  16
#define HEAD_DIM 64
#define BATCH    2
#define SEQ      2048
#define M_TOT    (BATCH * SEQ)   // 4096
#define WSZ      (D_MODEL * D_MODEL)

// ---------------- scratch (q/k/v hold fp16 bits; y/x/w hold bf16 bits) ----------------
__device__ __align__(1024) __nv_bfloat16 g_qhi[M_TOT * D_MODEL];
__device__ __align__(1024) __nv_bfloat16 g_qlo[M_TOT * D_MODEL];
__device__ __align__(1024) __nv_bfloat16 g_khi[M_TOT * D_MODEL];
__device__ __align__(1024) __nv_bfloat16 g_klo[M_TOT * D_MODEL];
__device__ __align__(1024) __nv_bfloat16 g_vhi[M_TOT * D_MODEL];
__device__ __align__(1024) __nv_bfloat16 g_vlo[M_TOT * D_MODEL];
__device__ __align__(1024) __nv_bfloat16 g_yhi[M_TOT * D_MODEL];
__device__ __align__(1024) __nv_bfloat16 g_ylo[M_TOT * D_MODEL];
__device__ __align__(1024) __nv_bfloat16 g_xhi[M_TOT * D_MODEL];
__device__ __align__(1024) __nv_bfloat16 g_xlo[M_TOT * D_MODEL];
__device__ __align__(1024) __nv_bfloat16 g_whi[4u * WSZ];
__device__ __align__(1024) __nv_bfloat16 g_wlo[4u * WSZ];

// ---------------- helpers ----------------
__device__ __forceinline__ uint32_t smem_u32(const void* p) {
    uint32_t a;
    asm("{ .reg .u64 t; cvta.to.shared.u64 t, %1; cvt.u32.u64 %0, t; }" : "=r"(a) : "l"(p));
    return a;
}
__device__ __forceinline__ uint32_t swz128(uint32_t off) { return off ^ ((off >> 3) & 0x70); }
__device__ __forceinline__ uint32_t swz64(uint32_t off)  { return off ^ ((off >> 3) & 0x30); }
__device__ __forceinline__ void cp16(uint32_t s, const void* g) {
    asm volatile("cp.async.cg.shared.global [%0], [%1], 16;" :: "r"(s), "l"(g));
}
#define CP_COMMIT() asm volatile("cp.async.commit_group;" ::: "memory")
#define CP_WAIT(n)  asm volatile("cp.async.wait_group %0;" :: "n"(n) : "memory")

__device__ __forceinline__ void ldsm4(uint32_t r[4], uint32_t addr) {
    asm volatile("ldmatrix.sync.aligned.m8n8.x4.shared.b16 {%0,%1,%2,%3}, [%4];"
                 : "=r"(r[0]), "=r"(r[1]), "=r"(r[2]), "=r"(r[3]) : "r"(addr));
}
__device__ __forceinline__ void ldsm4t(uint32_t r[4], uint32_t addr) {
    asm volatile("ldmatrix.sync.aligned.m8n8.x4.trans.shared.b16 {%0,%1,%2,%3}, [%4];"
                 : "=r"(r[0]), "=r"(r[1]), "=r"(r[2]), "=r"(r[3]) : "r"(addr));
}
__device__ __forceinline__ void mma_bf16(float d[4], const uint32_t a[4],
                                         uint32_t b0, uint32_t b1) {
    asm volatile(
        "mma.sync.aligned.m16n8k16.row.col.f32.bf16.bf16.f32 "
        "{%0,%1,%2,%3}, {%4,%5,%6,%7}, {%8,%9}, {%0,%1,%2,%3};"
        : "+f"(d[0]), "+f"(d[1]), "+f"(d[2]), "+f"(d[3])
        : "r"(a[0]), "r"(a[1]), "r"(a[2]), "r"(a[3]), "r"(b0), "r"(b1));
}
__device__ __forceinline__ void mma_f16(float d[4], const uint32_t a[4],
                                        uint32_t b0, uint32_t b1) {
    asm volatile(
        "mma.sync.aligned.m16n8k16.row.col.f32.f16.f16.f32 "
        "{%0,%1,%2,%3}, {%4,%5,%6,%7}, {%8,%9}, {%0,%1,%2,%3};"
        : "+f"(d[0]), "+f"(d[1]), "+f"(d[2]), "+f"(d[3])
        : "r"(a[0]), "r"(a[1]), "r"(a[2]), "r"(a[3]), "r"(b0), "r"(b1));
}
__device__ __forceinline__ uint32_t pack_bf16x2(float lo, float hi) {
    uint32_t r;
    asm("cvt.rn.bf16x2.f32 %0, %1, %2;" : "=r"(r) : "f"(hi), "f"(lo));
    return r;
}
__device__ __forceinline__ void split2(float v0, float v1, uint32_t& ph, uint32_t& pl) {
    ph = pack_bf16x2(v0, v1);
    float r0 = __uint_as_float(ph << 16);
    float r1 = __uint_as_float(ph & 0xffff0000u);
    pl = pack_bf16x2(v0 - r0, v1 - r1);
}
__device__ __forceinline__ uint32_t pack_f16x2(float v0, float v1) {
    __half2 h = __floats2half2_rn(v0, v1);
    return *reinterpret_cast<uint32_t*>(&h);
}
__device__ __forceinline__ void split2h(float v0, float v1, uint32_t& ph, uint32_t& pl) {
    __half h0 = __float2half_rn(v0), h1 = __float2half_rn(v1);
    __half2 hh = __halves2half2(h0, h1);
    ph = *reinterpret_cast<uint32_t*>(&hh);
    __half l0 = __float2half_rn(v0 - __half2float(h0));
    __half l1 = __float2half_rn(v1 - __half2float(h1));
    __half2 ll = __halves2half2(l0, l1);
    pl = *reinterpret_cast<uint32_t*>(&ll);
}

// ---------------- fused split: x + 4 weights (bf16) ----------------
#define XN4 (M_TOT * D_MODEL / 4)
#define WN4 (WSZ / 4)

__global__ __launch_bounds__(256) void split_all(
    const float4* __restrict__ x,
    const float4* __restrict__ wq, const float4* __restrict__ wk,
    const float4* __restrict__ wv, const float4* __restrict__ wp,
    __nv_bfloat162* __restrict__ xhi, __nv_bfloat162* __restrict__ xlo,
    __nv_bfloat162* __restrict__ whi, __nv_bfloat162* __restrict__ wlo)
{
    int i = blockIdx.x * 256 + threadIdx.x;
    const float4* src;
    __nv_bfloat162 *hi, *lo;
    int off;
    if (i < XN4) {
        src = x; off = i; hi = xhi; lo = xlo;
    } else {
        int j = i - XN4;
        int w = j >> 18;
        off = j & (WN4 - 1);
        src = (w == 0) ? wq : (w == 1) ? wk : (w == 2) ? wv : wp;
        hi = whi + (size_t)w * (WSZ / 2);
        lo = wlo + (size_t)w * (WSZ / 2);
    }
    float4 v = src[off];
    uint32_t h0, l0, h1, l1;
    split2(v.x, v.y, h0, l0);
    split2(v.z, v.w, h1, l1);
    *(uint32_t*)&hi[2 * off + 0] = h0;
    *(uint32_t*)&hi[2 * off + 1] = h1;
    *(uint32_t*)&lo[2 * off + 0] = l0;
    *(uint32_t*)&lo[2 * off + 1] = l1;
}

// ---------------- HMMA split-bf16 GEMM (BK=32, SW64, 3-stage, 1 sync/chunk) ----------------
// SPLIT=true: QKV launch, outputs packed fp16 hi/lo (for the fp16 attention).
#define T_B    8192
#define STG_B  (4 * T_B)
#define NSTG   3
#define GEMM_SMEM (NSTG * STG_B)      // 98304
#define KCHUNKS (D_MODEL / 32)        // 32

__device__ __forceinline__ void load_stage(
    uint32_t sbase, const __nv_bfloat16* a0, const __nv_bfloat16* a1,
    const __nv_bfloat16* b0, const __nv_bfloat16* b1, int kc, int tid)
{
    const __nv_bfloat16* gs[4] = {a0, a1, b0, b1};
    #pragma unroll
    for (int t = 0; t < 4; t++) {
        uint32_t tb = sbase + t * T_B;
        const __nv_bfloat16* g = gs[t] + kc * 32;
        #pragma unroll
        for (int i = 0; i < 2; i++) {
            int u = i * 256 + tid;
            int r = u >> 2, c4 = u & 3;
            cp16(tb + swz64(r * 64 + c4 * 16), g + (size_t)r * D_MODEL + c4 * 8);
        }
    }
}

template <bool SPLIT>
__global__ __launch_bounds__(256, 2) void gemm_hmma(
    const __nv_bfloat16* __restrict__ Ahi, const __nv_bfloat16* __restrict__ Alo,
    const __nv_bfloat16* __restrict__ Whi, const __nv_bfloat16* __restrict__ Wlo,
    const float* __restrict__ biasQ, const float* __restrict__ biasK,
    const float* __restrict__ biasV,
    float* __restrict__ C,
    __nv_bfloat16* __restrict__ QH, __nv_bfloat16* __restrict__ QL,
    __nv_bfloat16* __restrict__ KH, __nv_bfloat16* __restrict__ KL,
    __nv_bfloat16* __restrict__ VH, __nv_bfloat16* __restrict__ VL)
{
    extern __shared__ __align__(1024) char smem[];
    const uint32_t sb = smem_u32(smem);
    const int tid = threadIdx.x;
    const int wid = tid >> 5, lane = tid & 31;
    const int which = blockIdx.x >> 3;
    const int n0 = (blockIdx.x & 7) * 128;
    const int m0 = blockIdx.y * 128;
    const int wm = (wid >> 1) * 32;
    const int wn = (wid & 1) * 64;
    const int gid = lane >> 2, tig = lane & 3;

    const float* bias = (which == 0) ? biasQ : (which == 1) ? biasK : biasV;
    __nv_bfloat16* Chi = (which == 0) ? QH : (which == 1) ? KH : VH;
    __nv_bfloat16* Clo = (which == 0) ? QL : (which == 1) ? KL : VL;

    const __nv_bfloat16* a0 = Ahi + (size_t)m0 * D_MODEL;
    const __nv_bfloat16* a1 = Alo + (size_t)m0 * D_MODEL;
    const __nv_bfloat16* b0 = Whi + (size_t)which * WSZ + (size_t)n0 * D_MODEL;
    const __nv_bfloat16* b1 = Wlo + (size_t)which * WSZ + (size_t)n0 * D_MODEL;

    const int a_row  = wm + (lane & 15);
    const int a_byte = ((lane >> 4) & 1) * 16;
    const int b_row  = wn + ((lane >> 4) & 1) * 8 + (lane & 7);
    const int b_byte = ((lane >> 3) & 1) * 16;

    float d[2][8][4];
    #pragma unroll
    for (int i = 0; i < 2; i++)
        #pragma unroll
        for (int j = 0; j < 8; j++)
            #pragma unroll
            for (int c = 0; c < 4; c++) d[i][j][c] = 0.0f;

    load_stage(sb + 0 * STG_B, a0, a1, b0, b1, 0, tid);
    CP_COMMIT();
    load_stage(sb + 1 * STG_B, a0, a1, b0, b1, 1, tid);
    CP_COMMIT();

    for (int kc = 0; kc < KCHUNKS; kc++) {
        if (kc + 1 < KCHUNKS) { CP_WAIT(1); } else { CP_WAIT(0); }
        __syncthreads();
        if (kc + 2 < KCHUNKS) {
            load_stage(sb + ((kc + 2) % NSTG) * STG_B, a0, a1, b0, b1, kc + 2, tid);
            CP_COMMIT();
        }
        const uint32_t st = sb + (kc % NSTG) * STG_B;

        #pragma unroll
        for (int ks = 0; ks < 2; ks++) {
            uint32_t ah[2][4], al[2][4];
            #pragma unroll
            for (int am = 0; am < 2; am++) {
                uint32_t off = swz64((uint32_t)(a_row + am * 16) * 64 + a_byte + ks * 32);
                ldsm4(ah[am], st + off);
                ldsm4(al[am], st + T_B + off);
            }
            uint32_t bh[8][2], bl[8][2];
            #pragma unroll
            for (int pr = 0; pr < 4; pr++) {
                uint32_t off = swz64((uint32_t)(b_row + pr * 16) * 64 + b_byte + ks * 32);
                uint32_t r[4];
                ldsm4(r, st + 2 * T_B + off);
                bh[2 * pr][0] = r[0]; bh[2 * pr][1] = r[1];
                bh[2 * pr + 1][0] = r[2]; bh[2 * pr + 1][1] = r[3];
                ldsm4(r, st + 3 * T_B + off);
                bl[2 * pr][0] = r[0]; bl[2 * pr][1] = r[1];
                bl[2 * pr + 1][0] = r[2]; bl[2 * pr + 1][1] = r[3];
            }
            #pragma unroll
            for (int am = 0; am < 2; am++)
                #pragma unroll
                for (int bn = 0; bn < 8; bn++) {
                    mma_bf16(d[am][bn], ah[am], bh[bn][0], bh[bn][1]);
                    mma_bf16(d[am][bn], ah[am], bl[bn][0], bl[bn][1]);
                    mma_bf16(d[am][bn], al[am], bh[bn][0], bh[bn][1]);
                }
        }
    }

    #pragma unroll
    for (int am = 0; am < 2; am++) {
        const int row = m0 + wm + am * 16 + gid;
        #pragma unroll
        for (int bn = 0; bn < 8; bn++) {
            const int col = n0 + wn + bn * 8 + tig * 2;
            const float bv0 = __ldg(&bias[col]);
            const float bv1 = __ldg(&bias[col + 1]);
            float v0 = d[am][bn][0] + bv0, v1 = d[am][bn][1] + bv1;
            float v2 = d[am][bn][2] + bv0, v3 = d[am][bn][3] + bv1;
            if (SPLIT) {
                uint32_t h, l;
                split2h(v0, v1, h, l);    // fp16 hi/lo for attention
                *(uint32_t*)&Chi[(size_t)row * D_MODEL + col] = h;
                *(uint32_t*)&Clo[(size_t)row * D_MODEL + col] = l;
                split2h(v2, v3, h, l);
                *(uint32_t*)&Chi[(size_t)(row + 8) * D_MODEL + col] = h;
                *(uint32_t*)&Clo[(size_t)(row + 8) * D_MODEL + col] = l;
            } else {
                *(float2*)&C[(size_t)row * D_MODEL + col] = make_float2(v0, v1);
                *(float2*)&C[(size_t)(row + 8) * D_MODEL + col] = make_float2(v2, v3);
            }
        }
    }
}

// ---------------- HMMA flash attention (fp16, LPT, 2-stage) ----------------
// S = 3 fp16 products (err ~2^-22); PV = 2 products, P single fp16 (err ~2^-11).
#define AQ 128
#define KV_STG 32768
#define ATT_SMEM (2 * AQ * 128 + 2 * KV_STG)   // 98304

__global__ __launch_bounds__(256) void attn_hmma(
    const __nv_bfloat16* __restrict__ Qhi, const __nv_bfloat16* __restrict__ Qlo,
    const __nv_bfloat16* __restrict__ Khi, const __nv_bfloat16* __restrict__ Klo,
    const __nv_bfloat16* __restrict__ Vhi, const __nv_bfloat16* __restrict__ Vlo,
    __nv_bfloat16* __restrict__ Yhi, __nv_bfloat16* __restrict__ Ylo)
{
    extern __shared__ __align__(1024) char smA[];
    const uint32_t sb = smem_u32(smA);
    const int tid = threadIdx.x, wid = tid >> 5, lane = tid & 31;
    const int gid = lane >> 2, tig = lane & 3;
    const int qblk = gridDim.y - 1 - blockIdx.y;   // LPT
    const int bh = blockIdx.x;
    const int b = bh >> 4, h = bh & 15;
    const size_t base = ((size_t)b * SEQ) * D_MODEL + (size_t)h * HEAD_DIM;

    const uint32_t sQh = sb;
    const uint32_t sQl = sb + AQ * 128;
    const uint32_t sKV = sb + 2 * AQ * 128;

    {
        const __nv_bfloat16* q0 = Qhi + base + (size_t)qblk * AQ * D_MODEL;
        const __nv_bfloat16* q1 = Qlo + base + (size_t)qblk * AQ * D_MODEL;
        #pragma unroll
        for (int i = 0; i < 4; i++) {
            int u = i * 256 + tid;
            int r = u >> 3, c = u & 7;
            cp16(sQh + swz128(r * 128 + c * 16), q0 + (size_t)r * D_MODEL + c * 8);
            cp16(sQl + swz128(r * 128 + c * 16), q1 + (size_t)r * D_MODEL + c * 8);
        }
    }
    CP_COMMIT();

    const int nkt = 2 * qblk + 2;

    {
        const __nv_bfloat16* srcs[4] = {Khi + base, Klo + base, Vhi + base, Vlo + base};
        #pragma unroll
        for (int t = 0; t < 4; t++)
            #pragma unroll
            for (int i = 0; i < 2; i++) {
                int u = i * 256 + tid;
                int r = u >> 3, c = u & 7;
                cp16(sKV + t * 8192 + swz128(r * 128 + c * 16),
                     srcs[t] + (size_t)r * D_MODEL + c * 8);
            }
    }
    CP_COMMIT();
    CP_WAIT(1);
    __syncthreads();

    uint32_t qh[4][4], ql[4][4];
    {
        const int ar = wid * 16 + (lane & 15);
        const int ab = ((lane >> 4) & 1) * 16;
        #pragma unroll
        for (int ks = 0; ks < 4; ks++) {
            ldsm4(qh[ks], sQh + swz128((uint32_t)ar * 128 + ab + ks * 32));
            ldsm4(ql[ks], sQl + swz128((uint32_t)ar * 128 + ab + ks * 32));
        }
    }

    float o[8][4];
    #pragma unroll
    for (int nt = 0; nt < 8; nt++)
        #pragma unroll
        for (int j = 0; j < 4; j++) o[nt][j] = 0.0f;
    float m0 = -1e30f, m1 = -1e30f, l0 = 0.0f, l1 = 0.0f;

    const int qr0 = qblk * AQ + wid * 16 + gid;
    const int row_min = qblk * AQ + wid * 16;
    const int row_max = row_min + 15;

    const int sbr = ((lane >> 4) & 1) * 8 + (lane & 7);
    const int sbb = ((lane >> 3) & 1) * 16;
    const int vrr = lane & 15;
    const int vbb = ((lane >> 4) & 1) * 16;

    const float SC = 0.125f * 1.44269504f;

    for (int kt = 0; kt < nkt; kt++) {
        const uint32_t st = sKV + (uint32_t)(kt & 1) * KV_STG;
        __syncthreads();
        if (kt + 1 < nkt) {
            const size_t koff = base + (size_t)(kt + 1) * 64 * D_MODEL;
            const __nv_bfloat16* srcs[4] = {Khi + koff, Klo + koff, Vhi + koff, Vlo + koff};
            const uint32_t dst = sKV + (uint32_t)((kt + 1) & 1) * KV_STG;
            #pragma unroll
            for (int t = 0; t < 4; t++)
                #pragma unroll
                for (int i = 0; i < 2; i++) {
                    int u = i * 256 + tid;
                    int r = u >> 3, c = u & 7;
                    cp16(dst + t * 8192 + swz128(r * 128 + c * 16),
                         srcs[t] + (size_t)r * D_MODEL + c * 8);
                }
            CP_COMMIT();
            CP_WAIT(1);
        } else {
            CP_WAIT(0);
        }
        __syncthreads();

        if (kt * 64 > row_max) continue;

        // ---- S = Q K^T (fp16: hi*hi + hi*lo + lo*hi) ----
        float s[8][4];
        #pragma unroll
        for (int nt = 0; nt < 8; nt++)
            #pragma unroll
            for (int j = 0; j < 4; j++) s[nt][j] = 0.0f;

        #pragma unroll
        for (int ks = 0; ks < 4; ks++) {
            #pragma unroll
            for (int np = 0; np < 4; np++) {
                uint32_t off = swz128((uint32_t)(np * 16 + sbr) * 128 + sbb + ks * 32);
                uint32_t rh[4], rl[4];
                ldsm4(rh, st + off);
                ldsm4(rl, st + 8192 + off);
                mma_f16(s[2 * np],     qh[ks], rh[0], rh[1]);
                mma_f16(s[2 * np],     qh[ks], rl[0], rl[1]);
                mma_f16(s[2 * np],     ql[ks], rh[0], rh[1]);
                mma_f16(s[2 * np + 1], qh[ks], rh[2], rh[3]);
                mma_f16(s[2 * np + 1], qh[ks], rl[2], rl[3]);
                mma_f16(s[2 * np + 1], ql[ks], rh[2], rh[3]);
            }
        }

        const bool need_mask = (kt * 64 + 63 > row_min);
        #pragma unroll
        for (int nt = 0; nt < 8; nt++) {
            #pragma unroll
            for (int j = 0; j < 4; j++) s[nt][j] *= SC;
            if (need_mask) {
                const int kc = kt * 64 + nt * 8 + 2 * tig;
                if (kc     > qr0)     s[nt][0] = -1e30f;
                if (kc + 1 > qr0)     s[nt][1] = -1e30f;
                if (kc     > qr0 + 8) s[nt][2] = -1e30f;
                if (kc + 1 > qr0 + 8) s[nt][3] = -1e30f;
            }
        }

        // ---- online softmax (exp2 domain), P packed single fp16 ----
        float mx0 = -1e30f, mx1 = -1e30f;
        #pragma unroll
        for (int nt = 0; nt < 8; nt++) {
            mx0 = fmaxf(mx0, fmaxf(s[nt][0], s[nt][1]));
            mx1 = fmaxf(mx1, fmaxf(s[nt][2], s[nt][3]));
        }
        mx0 = fmaxf(mx0, __shfl_xor_sync(0xffffffffu, mx0, 1));
        mx0 = fmaxf(mx0, __shfl_xor_sync(0xffffffffu, mx0, 2));
        mx1 = fmaxf(mx1, __shfl_xor_sync(0xffffffffu, mx1, 1));
        mx1 = fmaxf(mx1, __shfl_xor_sync(0xffffffffu, mx1, 2));
        const float nm0 = fmaxf(m0, mx0), nm1 = fmaxf(m1, mx1);
        const float c0 = exp2f(m0 - nm0), c1 = exp2f(m1 - nm1);
        m0 = nm0; m1 = nm1;

        uint32_t pA[8], pB[8];
        float la0 = 0.0f, la1 = 0.0f;
        #pragma unroll
        for (int nt = 0; nt < 8; nt++) {
            float p0 = exp2f(s[nt][0] - m0), p1 = exp2f(s[nt][1] - m0);
            float p2 = exp2f(s[nt][2] - m1), p3 = exp2f(s[nt][3] - m1);
            la0 += p0 + p1; la1 += p2 + p3;
            pA[nt] = pack_f16x2(p0, p1);
            pB[nt] = pack_f16x2(p2, p3);
        }
        la0 += __shfl_xor_sync(0xffffffffu, la0, 1);
        la0 += __shfl_xor_sync(0xffffffffu, la0, 2);
        la1 += __shfl_xor_sync(0xffffffffu, la1, 1);
        la1 += __shfl_xor_sync(0xffffffffu, la1, 2);
        l0 = l0 * c0 + la0;
        l1 = l1 * c1 + la1;
        #pragma unroll
        for (int nt = 0; nt < 8; nt++) {
            o[nt][0] *= c0; o[nt][1] *= c0;
            o[nt][2] *= c1; o[nt][3] *= c1;
        }

        // ---- O += P V (P fp16 single x V fp16 hi/lo: 2 products) ----
        #pragma unroll
        for (int kk = 0; kk < 4; kk++) {
            uint32_t aH[4] = {pA[2 * kk], pB[2 * kk], pA[2 * kk + 1], pB[2 * kk + 1]};
            #pragma unroll
            for (int np = 0; np < 4; np++) {
                uint32_t off = swz128((uint32_t)(kk * 16 + vrr) * 128 + vbb + np * 32);
                uint32_t rh[4], rl[4];
                ldsm4t(rh, st + 16384 + off);
                ldsm4t(rl, st + 24576 + off);
                mma_f16(o[2 * np],     aH, rh[0], rh[1]);
                mma_f16(o[2 * np],     aH, rl[0], rl[1]);
                mma_f16(o[2 * np + 1], aH, rh[2], rh[3]);
                mma_f16(o[2 * np + 1], aH, rl[2], rl[3]);
            }
        }
    }

    // ---- epilogue: normalize, split to bf16 hi/lo for out-proj ----
    const float i0 = 1.0f / l0, i1 = 1.0f / l1;
    const size_t r0a = base + (size_t)qr0 * D_MODEL;
    const size_t r1a = base + (size_t)(qr0 + 8) * D_MODEL;
    #pragma unroll
    for (int nt = 0; nt < 8; nt++) {
        const int col = nt * 8 + 2 * tig;
        uint32_t hjk, ljk;
        split2(o[nt][0] * i0, o[nt][1] * i0, hjk, ljk);
        *(uint32_t*)&Yhi[r0a + col] = hjk;
        *(uint32_t*)&Ylo[r0a + col] = ljk;
        split2(o[nt][2] * i1, o[nt][3] * i1, hjk, ljk);
        *(uint32_t*)&Yhi[r1a + col] = hjk;
        *(uint32_t*)&Ylo[r1a + col] = ljk;
    }
}

// ---------------- launch ----------------
extern "C" void kernel_launch(void* const* d_in, const int* in_sizes, int n_in,
                              void* d_out, int out_size)
{
    const float* x  = (const float*)d_in[0];
    const float* Wq = (const float*)d_in[1];
    const float* bq = (const float*)d_in[2];
    const float* Wk = (const float*)d_in[3];
    const float* bk = (const float*)d_in[4];
    const float* Wv = (const float*)d_in[5];
    const float* bv = (const float*)d_in[6];
    const float* Wp = (const float*)d_in[7];
    const float* bp = (const float*)d_in[8];
    float* out = (float*)d_out;

    __nv_bfloat16 *qhi, *qlo, *khi, *klo, *vhi, *vlo, *yhi, *ylo, *xhi, *xlo, *whi, *wlo;
    cudaGetSymbolAddress((void**)&qhi, g_qhi);
    cudaGetSymbolAddress((void**)&qlo, g_qlo);
    cudaGetSymbolAddress((void**)&khi, g_khi);
    cudaGetSymbolAddress((void**)&klo, g_klo);
    cudaGetSymbolAddress((void**)&vhi, g_vhi);
    cudaGetSymbolAddress((void**)&vlo, g_vlo);
    cudaGetSymbolAddress((void**)&yhi, g_yhi);
    cudaGetSymbolAddress((void**)&ylo, g_ylo);
    cudaGetSymbolAddress((void**)&xhi, g_xhi);
    cudaGetSymbolAddress((void**)&xlo, g_xlo);
    cudaGetSymbolAddress((void**)&whi, g_whi);
    cudaGetSymbolAddress((void**)&wlo, g_wlo);

    cudaFuncSetAttribute(gemm_hmma<true>,
                         cudaFuncAttributeMaxDynamicSharedMemorySize, GEMM_SMEM);
    cudaFuncSetAttribute(gemm_hmma<false>,
                         cudaFuncAttributeMaxDynamicSharedMemorySize, GEMM_SMEM);
    cudaFuncSetAttribute(attn_hmma,
                         cudaFuncAttributeMaxDynamicSharedMemorySize, ATT_SMEM);

    split_all<<<(XN4 + 4 * WN4) / 256, 256>>>(
        (const float4*)x, (const float4*)Wq, (const float4*)Wk,
        (const float4*)Wv, (const float4*)Wp,
        (__nv_bfloat162*)xhi, (__nv_bfloat162*)xlo,
        (__nv_bfloat162*)whi, (__nv_bfloat162*)wlo);

    gemm_hmma<true><<<dim3(24, 32), 256, GEMM_SMEM>>>(
        xhi, xlo, whi, wlo, bq, bk, bv,
        nullptr, qhi, qlo, khi, klo, vhi, vlo);

    attn_hmma<<<dim3(BATCH * N_HEADS, SEQ / AQ), 256, ATT_SMEM>>>(
        qhi, qlo, khi, klo, vhi, vlo, yhi, ylo);

    gemm_hmma<false><<<dim3(8, 32), 256, GEMM_SMEM>>>(
        yhi, ylo, whi + 3u * WSZ, wlo + 3u * WSZ, bp, nullptr, nullptr,
        out, nullptr, nullptr, nullptr, nullptr, nullptr, nullptr);
}